// round 1
// baseline (speedup 1.0000x reference)
#include <cuda_runtime.h>
#include <cuda_bf16.h>
#include <math.h>

#define KBINS 5
#define TAILB 2.5f
#define TPB 256

// Precomputed per-bin tables (written by setup kernel, read by main kernel).
// t0: {x_k, 1/(W+1e-8), y_k, dy}
// t1: {d_k, d_k1, s_k, c = d_k+d_k1-2*s_k}
// t2: {2*log(s_k+1e-8), 2*s_k, 0, 0}
__device__ float4 g_t0[KBINS];
__device__ float4 g_t1[KBINS];
__device__ float4 g_t2[KBINS];
__device__ float  g_bnd[4];   // interior bin boundaries cum_w[1..4]

__global__ void rqs_setup_kernel(const float* __restrict__ params) {
    if (threadIdx.x != 0) return;

    float W[KBINS], H[KBINS], D[KBINS + 1];

    // softmax(widths) * 2*TAILB
    {
        float mx = params[0];
        #pragma unroll
        for (int i = 1; i < KBINS; i++) mx = fmaxf(mx, params[i]);
        float s = 0.f, e[KBINS];
        #pragma unroll
        for (int i = 0; i < KBINS; i++) { e[i] = expf(params[i] - mx); s += e[i]; }
        #pragma unroll
        for (int i = 0; i < KBINS; i++) W[i] = e[i] / s * (2.0f * TAILB);
    }
    // softmax(heights) * 2*TAILB
    {
        float mx = params[KBINS];
        #pragma unroll
        for (int i = 1; i < KBINS; i++) mx = fmaxf(mx, params[KBINS + i]);
        float s = 0.f, e[KBINS];
        #pragma unroll
        for (int i = 0; i < KBINS; i++) { e[i] = expf(params[KBINS + i] - mx); s += e[i]; }
        #pragma unroll
        for (int i = 0; i < KBINS; i++) H[i] = e[i] / s * (2.0f * TAILB);
    }
    // softplus(derivs) + 1e-5
    #pragma unroll
    for (int i = 0; i < KBINS + 1; i++) {
        float v = params[2 * KBINS + i];
        D[i] = log1pf(expf(-fabsf(v))) + fmaxf(v, 0.0f) + 1e-5f;
    }

    float cw[KBINS + 1], ch[KBINS + 1];
    cw[0] = -TAILB; ch[0] = -TAILB;
    float aw = 0.f, ah = 0.f;
    #pragma unroll
    for (int i = 0; i < KBINS; i++) {
        aw += W[i]; cw[i + 1] = aw - TAILB;
        ah += H[i]; ch[i + 1] = ah - TAILB;
    }

    #pragma unroll
    for (int b = 0; b < KBINS; b++) {
        float winv = 1.0f / (cw[b + 1] - cw[b] + 1e-8f);
        float dy   = ch[b + 1] - ch[b];
        float s    = H[b] / W[b];
        g_t0[b] = make_float4(cw[b], winv, ch[b], dy);
        g_t1[b] = make_float4(D[b], D[b + 1], s, D[b] + D[b + 1] - 2.0f * s);
        g_t2[b] = make_float4(2.0f * logf(s + 1e-8f), 2.0f * s, 0.f, 0.f);
    }
    #pragma unroll
    for (int i = 0; i < 4; i++) g_bnd[i] = cw[i + 1];
}

// FMA-only log: exponent extraction + Cephes minimax polynomial on [sqrt(.5),sqrt(2))
__device__ __forceinline__ float fast_logf(float a) {
    int ia = __float_as_int(a);
    int e  = (ia - 0x3f3504f3) & 0xff800000;
    float m  = __int_as_float(ia - e);
    float fe = (float)(e >> 23);
    float f  = m - 1.0f;
    float z  = f * f;
    float p  =              7.0376836292e-2f;
    p = fmaf(p, f, -1.1514610310e-1f);
    p = fmaf(p, f,  1.1676998740e-1f);
    p = fmaf(p, f, -1.2420140846e-1f);
    p = fmaf(p, f,  1.4249322787e-1f);
    p = fmaf(p, f, -1.6668057665e-1f);
    p = fmaf(p, f,  2.0000714765e-1f);
    p = fmaf(p, f, -2.4999993993e-1f);
    p = fmaf(p, f,  3.3333331174e-1f);
    float y = f * z * p;
    y = fmaf(-0.5f, z, y);
    return fmaf(fe, 0.69314718056f, f + y);
}

// MUFU-free reciprocal: bit-magic seed + 3 Newton iterations (valid for d > 0)
__device__ __forceinline__ float fast_rcp(float d) {
    float r = __int_as_float(0x7EF311C3 - __float_as_int(d));
    r = r * fmaf(-d, r, 2.0f);
    r = r * fmaf(-d, r, 2.0f);
    r = r * fmaf(-d, r, 2.0f);
    return r;
}

__device__ __forceinline__ void rqs_one(
    float x, float b0, float b1, float b2, float b3,
    const float4* __restrict__ s0, const float4* __restrict__ s1,
    const float4* __restrict__ s2, float& zo, float& lo)
{
    bool inside = fabsf(x) <= TAILB;
    float xs = inside ? x : 0.0f;
    int b = (xs > b0) + (xs > b1) + (xs > b2) + (xs > b3);

    float4 t0 = s0[b];
    float4 t1 = s1[b];
    float4 t2 = s2[b];

    float xi  = __saturatef((xs - t0.x) * t0.y);
    float omx = 1.0f - xi;
    float tt  = xi * omx;

    float denom = fmaf(t1.w, tt, t1.z);            // s + c*t  (> 0 always)
    float r     = fast_rcp(denom);

    float dkomx = t1.x * omx;
    float num   = xi * fmaf(t1.z, xi, dkomx);      // s*xi^2 + dk*xi*omx
    float z     = fmaf(t0.w * num, r, t0.z);       // y_k + dy*num/denom

    float num2  = fmaf(t1.y * xi, xi, fmaf(t2.y, tt, dkomx * omx)); // dk1*xi^2 + 2s*t + dk*omx^2
    float larg  = (num2 * r) * r;
    float lj    = t2.x + fast_logf(larg);          // 2*log(s_k) + log(num2/denom^2)

    zo = inside ? z : x;
    lo = inside ? lj : 0.0f;
}

__global__ void __launch_bounds__(TPB)
rqs_main_kernel(const float* __restrict__ x, float* __restrict__ out, int n4)
{
    __shared__ float4 s0[KBINS], s1[KBINS], s2[KBINS];
    int tid = threadIdx.x;
    if (tid < KBINS) {
        s0[tid] = g_t0[tid];
        s1[tid] = g_t1[tid];
        s2[tid] = g_t2[tid];
    }
    __syncthreads();

    // uniform boundary values (L1-resident)
    float b0 = g_bnd[0], b1 = g_bnd[1], b2 = g_bnd[2], b3 = g_bnd[3];

    const float4* __restrict__ x4 = (const float4*)x;
    float4* __restrict__ z4 = (float4*)out;
    float4* __restrict__ l4 = (float4*)(out + ((size_t)n4 * 4));

    int stride = gridDim.x * blockDim.x;
    for (int i = blockIdx.x * TPB + tid; i < n4; i += stride) {
        float4 xv = x4[i];
        float4 zv, lv;
        rqs_one(xv.x, b0, b1, b2, b3, s0, s1, s2, zv.x, lv.x);
        rqs_one(xv.y, b0, b1, b2, b3, s0, s1, s2, zv.y, lv.y);
        rqs_one(xv.z, b0, b1, b2, b3, s0, s1, s2, zv.z, lv.z);
        rqs_one(xv.w, b0, b1, b2, b3, s0, s1, s2, zv.w, lv.w);
        z4[i] = zv;
        l4[i] = lv;
    }
}

extern "C" void kernel_launch(void* const* d_in, const int* in_sizes, int n_in,
                              void* d_out, int out_size)
{
    const float* x      = (const float*)d_in[0];
    const float* params = (const float*)d_in[1];
    float* out          = (float*)d_out;

    int n  = in_sizes[0];     // 16777216
    int n4 = n >> 2;          // float4 count

    rqs_setup_kernel<<<1, 32>>>(params);

    // 2 float4 per thread
    int blocks = (n4 + TPB * 2 - 1) / (TPB * 2);
    rqs_main_kernel<<<blocks, TPB>>>(x, out, n4);
}

// round 2
// speedup vs baseline: 1.0484x; 1.0484x over previous
#include <cuda_runtime.h>
#include <cuda_bf16.h>
#include <math.h>

#define KBINS 5
#define TAILB 2.5f
#define TPB 256

// Per-bin quadratic coefficient tables (in x), written by setup kernel:
//   g_tab[3b+0] = {p2, p1, p0, y_k}      den(x)  = p2 x^2 + p1 x + p0
//   g_tab[3b+1] = {q2, q1, q0, 2log(s)}  numz(x) = q2 x^2 + q1 x + q0   (dy folded in)
//   g_tab[3b+2] = {r2, r1, r0, 0}        num2(x) = r2 x^2 + r1 x + r0
__device__ float4 g_tab[3 * KBINS];
__device__ float  g_bnd[4];   // interior bin boundaries cum_w[1..4]

__global__ void rqs_setup_kernel(const float* __restrict__ params) {
    if (threadIdx.x != 0) return;

    float W[KBINS], H[KBINS], D[KBINS + 1];

    { // softmax(widths) * 2*TAILB
        float mx = params[0];
        #pragma unroll
        for (int i = 1; i < KBINS; i++) mx = fmaxf(mx, params[i]);
        float s = 0.f, e[KBINS];
        #pragma unroll
        for (int i = 0; i < KBINS; i++) { e[i] = expf(params[i] - mx); s += e[i]; }
        #pragma unroll
        for (int i = 0; i < KBINS; i++) W[i] = e[i] / s * (2.0f * TAILB);
    }
    { // softmax(heights) * 2*TAILB
        float mx = params[KBINS];
        #pragma unroll
        for (int i = 1; i < KBINS; i++) mx = fmaxf(mx, params[KBINS + i]);
        float s = 0.f, e[KBINS];
        #pragma unroll
        for (int i = 0; i < KBINS; i++) { e[i] = expf(params[KBINS + i] - mx); s += e[i]; }
        #pragma unroll
        for (int i = 0; i < KBINS; i++) H[i] = e[i] / s * (2.0f * TAILB);
    }
    #pragma unroll
    for (int i = 0; i < KBINS + 1; i++) { // softplus + 1e-5
        float v = params[2 * KBINS + i];
        D[i] = log1pf(expf(-fabsf(v))) + fmaxf(v, 0.0f) + 1e-5f;
    }

    float cw[KBINS + 1], ch[KBINS + 1];
    cw[0] = -TAILB; ch[0] = -TAILB;
    float aw = 0.f, ah = 0.f;
    #pragma unroll
    for (int i = 0; i < KBINS; i++) {
        aw += W[i]; cw[i + 1] = aw - TAILB;
        ah += H[i]; ch[i + 1] = ah - TAILB;
    }

    #pragma unroll
    for (int bi = 0; bi < KBINS; bi++) {
        float xk  = cw[bi];
        float yk  = ch[bi];
        float dy  = ch[bi + 1] - ch[bi];
        float dk  = D[bi], dk1 = D[bi + 1];
        float s   = H[bi] / W[bi];
        float c   = dk + dk1 - 2.0f * s;
        // xi = a*x + b
        float a = 1.0f / (cw[bi + 1] - cw[bi] + 1e-8f);
        float b = -a * xk;

        // den = -c v^2 + c v + s,  v = a x + b
        float p2 = -c * a * a;
        float p1 = c * a * (1.0f - 2.0f * b);
        float p0 = s + c * (b - b * b);
        // numz = dy*((s-dk) v^2 + dk v)
        float sd = s - dk;
        float q2 = dy * sd * a * a;
        float q1 = dy * a * (2.0f * b * sd + dk);
        float q0 = dy * (sd * b * b + dk * b);
        // num2 = c v^2 + 2(s-dk) v + dk
        float r2 = c * a * a;
        float r1 = 2.0f * a * (c * b + sd);
        float r0 = c * b * b + 2.0f * sd * b + dk;

        g_tab[3 * bi + 0] = make_float4(p2, p1, p0, yk);
        g_tab[3 * bi + 1] = make_float4(q2, q1, q0, 2.0f * logf(s + 1e-8f));
        g_tab[3 * bi + 2] = make_float4(r2, r1, r0, 0.0f);
    }
    #pragma unroll
    for (int i = 0; i < 4; i++) g_bnd[i] = cw[i + 1];
}

// MUFU-free reciprocal: bit-magic seed + 2 Newton iterations (d > 0, moderate range)
__device__ __forceinline__ float fast_rcp(float d) {
    float r = __int_as_float(0x7EF311C3 - __float_as_int(d));
    r = r * fmaf(-d, r, 2.0f);
    r = r * fmaf(-d, r, 2.0f);
    return r;
}

__device__ __forceinline__ void rqs_one(
    float x, float b0, float b1, float b2, float b3,
    const float4* __restrict__ sh, float& zo, float& lo)
{
    bool inside = fabsf(x) <= TAILB;
    float xs = inside ? x : 0.0f;
    int off = ((xs > b0) + (xs > b1) + (xs > b2) + (xs > b3)) * 3;

    float4 T0 = sh[off];
    float4 T1 = sh[off + 1];
    float4 T2 = sh[off + 2];

    float den  = fmaf(fmaf(T0.x, xs, T0.y), xs, T0.z);
    float numz = fmaf(fmaf(T1.x, xs, T1.y), xs, T1.z);
    float num2 = fmaf(fmaf(T2.x, xs, T2.y), xs, T2.z);

    float A = fast_rcp(den);
    float z = fmaf(numz, A, T0.w);          // y_k + numz/den

    float d2 = den * den;
    float B  = fast_rcp(num2 + d2);
    float u  = (num2 - d2) * B;             // (larg-1)/(larg+1), larg = num2/den^2
    float u2 = u * u;
    // log(larg) = 2*atanh(u) = u*(2 + u^2*(2/3 + u^2*(2/5 + u^2*2/7)))
    float p = fmaf(u2, 0.2857142857f, 0.4f);
    p = fmaf(p, u2, 0.6666666667f);
    p = fmaf(p, u2, 2.0f);
    float lj = fmaf(u, p, T1.w);            // + 2*log(s_k)

    zo = inside ? z : x;
    lo = inside ? lj : 0.0f;
}

__global__ void __launch_bounds__(TPB)
rqs_main_kernel(const float* __restrict__ x, float* __restrict__ out, int n4)
{
    __shared__ float4 sh[3 * KBINS];
    int tid = threadIdx.x;
    if (tid < 3 * KBINS) sh[tid] = g_tab[tid];
    __syncthreads();

    float b0 = g_bnd[0], b1 = g_bnd[1], b2 = g_bnd[2], b3 = g_bnd[3];

    const float4* __restrict__ x4 = (const float4*)x;
    float4* __restrict__ z4 = (float4*)out;
    float4* __restrict__ l4 = (float4*)(out + ((size_t)n4 * 4));

    int base = blockIdx.x * (TPB * 2) + tid;

    #pragma unroll
    for (int k = 0; k < 2; k++) {
        int i = base + k * TPB;
        if (i < n4) {
            float4 xv = x4[i];
            float4 zv, lv;
            rqs_one(xv.x, b0, b1, b2, b3, sh, zv.x, lv.x);
            rqs_one(xv.y, b0, b1, b2, b3, sh, zv.y, lv.y);
            rqs_one(xv.z, b0, b1, b2, b3, sh, zv.z, lv.z);
            rqs_one(xv.w, b0, b1, b2, b3, sh, zv.w, lv.w);
            z4[i] = zv;
            l4[i] = lv;
        }
    }
}

extern "C" void kernel_launch(void* const* d_in, const int* in_sizes, int n_in,
                              void* d_out, int out_size)
{
    const float* x      = (const float*)d_in[0];
    const float* params = (const float*)d_in[1];
    float* out          = (float*)d_out;

    int n  = in_sizes[0];     // 16777216
    int n4 = n >> 2;          // float4 count

    rqs_setup_kernel<<<1, 32>>>(params);

    int blocks = (n4 + TPB * 2 - 1) / (TPB * 2);
    rqs_main_kernel<<<blocks, TPB>>>(x, out, n4);
}

// round 3
// speedup vs baseline: 1.2385x; 1.1813x over previous
#include <cuda_runtime.h>
#include <cuda_bf16.h>
#include <math.h>

#define KBINS 5
#define TAILB 2.5f
#define TPB 256

// Per-bin table, 2 float4 used + 1 float4 pad (48B stride -> conflict-free LDS):
//   g_tab[3b+0] = A = {p2', p1', p0', q2'}   den'(x)  = p2'x^2+p1'x+p0'
//   g_tab[3b+1] = B = {q1', q0', r1', r0'}   numz'(x) = q2'x^2+q1'x+q0' (y_k folded)
//                                            num2'(x) = -p2'x^2+r1'x+r0' (identity)
// All scaled by 1/s^2 so that lj = log(num2'/den'^2) exactly (2*log s folded).
__device__ float4 g_tab[3 * KBINS];
__device__ float  g_bnd[4];   // interior bin boundaries cum_w[1..4]

__global__ void rqs_setup_kernel(const float* __restrict__ params) {
    if (threadIdx.x != 0) return;

    float W[KBINS], H[KBINS], D[KBINS + 1];

    { // softmax(widths) * 2*TAILB
        float mx = params[0];
        #pragma unroll
        for (int i = 1; i < KBINS; i++) mx = fmaxf(mx, params[i]);
        float s = 0.f, e[KBINS];
        #pragma unroll
        for (int i = 0; i < KBINS; i++) { e[i] = expf(params[i] - mx); s += e[i]; }
        #pragma unroll
        for (int i = 0; i < KBINS; i++) W[i] = e[i] / s * (2.0f * TAILB);
    }
    { // softmax(heights) * 2*TAILB
        float mx = params[KBINS];
        #pragma unroll
        for (int i = 1; i < KBINS; i++) mx = fmaxf(mx, params[KBINS + i]);
        float s = 0.f, e[KBINS];
        #pragma unroll
        for (int i = 0; i < KBINS; i++) { e[i] = expf(params[KBINS + i] - mx); s += e[i]; }
        #pragma unroll
        for (int i = 0; i < KBINS; i++) H[i] = e[i] / s * (2.0f * TAILB);
    }
    #pragma unroll
    for (int i = 0; i < KBINS + 1; i++) { // softplus + 1e-5
        float v = params[2 * KBINS + i];
        D[i] = log1pf(expf(-fabsf(v))) + fmaxf(v, 0.0f) + 1e-5f;
    }

    float cw[KBINS + 1], ch[KBINS + 1];
    cw[0] = -TAILB; ch[0] = -TAILB;
    float aw = 0.f, ah = 0.f;
    #pragma unroll
    for (int i = 0; i < KBINS; i++) {
        aw += W[i]; cw[i + 1] = aw - TAILB;
        ah += H[i]; ch[i + 1] = ah - TAILB;
    }

    #pragma unroll
    for (int bi = 0; bi < KBINS; bi++) {
        float xk  = cw[bi];
        float yk  = ch[bi];
        float dy  = ch[bi + 1] - ch[bi];
        float dk  = D[bi], dk1 = D[bi + 1];
        float s   = H[bi] / W[bi];
        float c   = dk + dk1 - 2.0f * s;
        float sd  = s - dk;
        // xi = a*x + b_
        float a  = 1.0f / (cw[bi + 1] - cw[bi] + 1e-8f);
        float b_ = -a * xk;

        // den = -c v^2 + c v + s
        float p2 = -c * a * a;
        float p1 = c * a * (1.0f - 2.0f * b_);
        float p0 = s + c * (b_ - b_ * b_);
        // numz = dy*(sd v^2 + dk v), then fold y_k: q^ = q + yk*p
        float q2 = dy * sd * a * a + yk * p2;
        float q1 = dy * a * (2.0f * b_ * sd + dk) + yk * p1;
        float q0 = dy * (sd * b_ * b_ + dk * b_) + yk * p0;
        // num2 = c v^2 + 2 sd v + dk
        float r1 = 2.0f * a * (c * b_ + sd);
        float r0 = c * b_ * b_ + 2.0f * sd * b_ + dk;
        // (r2 = c a^2 = -p2; after common 1/s^2 scaling: r2' = -p2' — derived at runtime)

        float is2 = 1.0f / (s * s);
        g_tab[3 * bi + 0] = make_float4(p2 * is2, p1 * is2, p0 * is2, q2 * is2);
        g_tab[3 * bi + 1] = make_float4(q1 * is2, q0 * is2, r1 * is2, r0 * is2);
        g_tab[3 * bi + 2] = make_float4(0.f, 0.f, 0.f, 0.f);  // pad (bank spread)
    }
    #pragma unroll
    for (int i = 0; i < 4; i++) g_bnd[i] = cw[i + 1];
}

// MUFU-free reciprocal: bit-magic seed + 2 Newton iterations (d > 0)
__device__ __forceinline__ float fast_rcp(float d) {
    float r = __int_as_float(0x7EF311C3 - __float_as_int(d));
    r = r * fmaf(-d, r, 2.0f);
    r = r * fmaf(-d, r, 2.0f);
    return r;
}

__device__ __forceinline__ void rqs_one(
    float x, float b0, float b1, float b2, float b3,
    const float4* __restrict__ sh, float& zo, float& lo)
{
    bool inside = fabsf(x) <= TAILB;
    float xs = inside ? x : 0.0f;
    int off = ((xs > b0) + (xs > b1) + (xs > b2) + (xs > b3)) * 3;

    float4 A = sh[off];
    float4 B = sh[off + 1];

    float den  = fmaf(fmaf(A.x, xs, A.y), xs, A.z);
    float numz = fmaf(fmaf(A.w, xs, B.x), xs, B.y);
    float num2 = fmaf(fmaf(-A.x, xs, B.z), xs, B.w);

    float rA = fast_rcp(den);
    float z  = numz * rA;                   // y_k already folded in

    float d2  = den * den;
    float rB  = fast_rcp(num2 + d2);
    float u   = (num2 - d2) * rB;           // tanh(lj/2)
    float u2  = u * u;
    // lj = 2*atanh(u) = u*(2 + u^2*(2/3 + u^2*(2/5 + u^2*(2/7))))
    float p = fmaf(u2, 0.2857142857f, 0.4f);
    p = fmaf(p, u2, 0.6666666667f);
    p = fmaf(p, u2, 2.0f);
    float lj = u * p;

    zo = inside ? z : x;
    lo = inside ? lj : 0.0f;
}

__global__ void __launch_bounds__(TPB)
rqs_main_kernel(const float* __restrict__ x, float* __restrict__ out, int n4)
{
    __shared__ float4 sh[3 * KBINS];
    int tid = threadIdx.x;
    if (tid < 3 * KBINS) sh[tid] = g_tab[tid];
    __syncthreads();

    float b0 = g_bnd[0], b1 = g_bnd[1], b2 = g_bnd[2], b3 = g_bnd[3];

    const float4* __restrict__ x4 = (const float4*)x;
    float4* __restrict__ z4 = (float4*)out;
    float4* __restrict__ l4 = (float4*)(out + ((size_t)n4 * 4));

    int base = blockIdx.x * (TPB * 2) + tid;

    #pragma unroll
    for (int k = 0; k < 2; k++) {
        int i = base + k * TPB;
        if (i < n4) {
            float4 xv = x4[i];
            float4 zv, lv;
            rqs_one(xv.x, b0, b1, b2, b3, sh, zv.x, lv.x);
            rqs_one(xv.y, b0, b1, b2, b3, sh, zv.y, lv.y);
            rqs_one(xv.z, b0, b1, b2, b3, sh, zv.z, lv.z);
            rqs_one(xv.w, b0, b1, b2, b3, sh, zv.w, lv.w);
            z4[i] = zv;
            l4[i] = lv;
        }
    }
}

extern "C" void kernel_launch(void* const* d_in, const int* in_sizes, int n_in,
                              void* d_out, int out_size)
{
    const float* x      = (const float*)d_in[0];
    const float* params = (const float*)d_in[1];
    float* out          = (float*)d_out;

    int n  = in_sizes[0];     // 16777216
    int n4 = n >> 2;          // float4 count

    rqs_setup_kernel<<<1, 32>>>(params);

    int blocks = (n4 + TPB * 2 - 1) / (TPB * 2);
    rqs_main_kernel<<<blocks, TPB>>>(x, out, n4);
}